// round 8
// baseline (speedup 1.0000x reference)
#include <cuda_runtime.h>

// TorchGrouper — round 7: round-6 pipeline (persistent blocks, prefetched
// voxel lookups) + fully bank-conflict-free lane mappings for both smem
// phases (scalar STS/LDS, stride-65 tile; banks verified: 65=1, 260=4 mod 32).
// Output: [C,G,K] features, [4,G,K] gpf, [G] mask (float 1/0).

#define ZDIM 40
#define YDIM 400
#define XDIM 400
#define KK 64
#define CC 64
#define TPB 256
#define NBLK 1184        // 148 SMs x 8 resident blocks
#define TS 65            // tile row stride (floats)

__global__ __launch_bounds__(TPB, 8) void grouper_kernel(
    const int* __restrict__ vox,     // [N,Z,Y,X]
    const int* __restrict__ gpos,    // [G,4]
    const float* __restrict__ feat,  // [M,C]
    const int* __restrict__ off,     // [K,4]
    float* __restrict__ out,
    int G)
{
    __shared__ int      s_idx[2][KK];
    __shared__ unsigned s_ball[2][2];
    __shared__ float    s_tile[KK * TS];

    const int t    = threadIdx.x;
    const int w    = t >> 5;
    const int lane = t & 31;
    const size_t GK = (size_t)G * KK;
    float* out_gpf  = out + (size_t)CC * GK;
    float* out_mask = out + (size_t)(CC + 4) * GK;
    const float4* feat4 = reinterpret_cast<const float4*>(feat);

    // loop-invariant per-thread constants
    const int gpf_ch = t >> 6;           // 0..3
    const int gpf_k  = t & 63;
    const float gpf_val = (float)off[gpf_k * 4 + gpf_ch];
    int4 of = make_int4(0, 0, 0, 0);
    if (t < KK) of = reinterpret_cast<const int4*>(off)[t];

    // gather mapping: lane -> (koff, cq)
    const int koff = lane & 3;           // k within 4-row group
    const int cqg  = lane >> 2;          // 0..7 c-quad within half
    // drain mapping: lane -> (ql, dc)
    const int ql = lane & 7;             // k-quad low bits
    const int dc = lane >> 3;            // 0..3 c offset

    // ---- prologue: lookup for first g ----
    int g = blockIdx.x;
    if (t < KK) {
        const int4 gp = reinterpret_cast<const int4*>(gpos)[g];
        int z = min(max(gp.y + of.y, 0), ZDIM - 1);
        int y = min(max(gp.z + of.z, 0), YDIM - 1);
        int x = min(max(gp.w + of.w, 0), XDIM - 1);
        int idx = vox[((gp.x * ZDIM + z) * YDIM + y) * XDIM + x];
        s_idx[0][t] = idx;
        unsigned m = __ballot_sync(0xffffffffu, idx >= 0);
        if (lane == 0) s_ball[0][w] = m;
    }
    __syncthreads();

    int p = 0;
    for (; g < G; g += NBLK) {
        const int g_next = g + NBLK;
        const bool has_next = (g_next < G);

        // ---- prefetch next g's voxel lookups into registers ----
        int idxnext = -1;
        if (t < KK && has_next) {
            const int4 gp = reinterpret_cast<const int4*>(gpos)[g_next];
            int z = min(max(gp.y + of.y, 0), ZDIM - 1);
            int y = min(max(gp.z + of.z, 0), YDIM - 1);
            int x = min(max(gp.w + of.w, 0), XDIM - 1);
            idxnext = vox[((gp.x * ZDIM + z) * YDIM + y) * XDIM + x];
        }

        // ---- gather current g: feature rows -> tile[k][c], CF STS ----
#pragma unroll
        for (int j = 0; j < 4; j++) {
            const int task  = w * 4 + j;             // 0..31
            const int k0    = (task & 15) * 4;       // 0..60
            const int chalf = task >> 4;             // 0..1
            const int k     = k0 + koff;
            const int cq    = chalf * 8 + cqg;       // 0..15
            const int idx   = s_idx[p][k];
            float4 v = make_float4(0.f, 0.f, 0.f, 0.f);
            if (idx >= 0) v = feat4[(size_t)idx * (CC / 4) + cq];
            float* dst = &s_tile[k * TS + cq * 4];
            dst[0] = v.x; dst[1] = v.y; dst[2] = v.z; dst[3] = v.w;
        }
        __syncthreads();

        // ---- drain: transposed float4 streaming stores, CF LDS ----
#pragma unroll
        for (int j = 0; j < 4; j++) {
            const int task = w * 4 + j;              // 0..31
            const int c0   = (task & 15) * 4;        // 0..60
            const int qh   = task >> 4;              // 0..1
            const int q    = qh * 8 + ql;            // 0..15
            const int c    = c0 + dc;
            float4 v;
            v.x = s_tile[(q * 4 + 0) * TS + c];
            v.y = s_tile[(q * 4 + 1) * TS + c];
            v.z = s_tile[(q * 4 + 2) * TS + c];
            v.w = s_tile[(q * 4 + 3) * TS + c];
            __stcs(reinterpret_cast<float4*>(
                       out + (size_t)c * GK + (size_t)g * KK + q * 4), v);
        }

        // ---- gpf + mask for current g ----
        __stcs(out_gpf + (size_t)gpf_ch * GK + (size_t)g * KK + gpf_k, gpf_val);
        if (t == 0)
            out_mask[g] = ((s_ball[p][0] | s_ball[p][1]) == 0u) ? 1.0f : 0.0f;

        // ---- publish prefetched lookups into the other buffer ----
        if (t < KK && has_next) {
            s_idx[1 - p][t] = idxnext;
            unsigned m = __ballot_sync(0xffffffffu, idxnext >= 0);
            if (lane == 0) s_ball[1 - p][w] = m;
        }
        __syncthreads();
        p ^= 1;
    }
}

extern "C" void kernel_launch(void* const* d_in, const int* in_sizes, int n_in,
                              void* d_out, int out_size) {
    const int*   vox  = (const int*)d_in[0];
    const int*   gpos = (const int*)d_in[1];
    const float* feat = (const float*)d_in[2];
    const int*   off  = (const int*)d_in[3];
    float* out = (float*)d_out;

    const int G = in_sizes[1] / 4;   // 30000
    grouper_kernel<<<NBLK, TPB>>>(vox, gpos, feat, off, out, G);
}

// round 9
// speedup vs baseline: 1.8167x; 1.8167x over previous
#include <cuda_runtime.h>

// TorchGrouper — round 9: identical to round 6 (best: 133.9us) except the
// drain lane mapping, now bank-conflict-free:
//   lane -> (ql = lane&7 -> k-quad, dc = lane>>3 -> c offset)
//   LDS bank for component r: (4*ql + dc + r + c0) mod 32 -> 32 distinct.
// Gather phase untouched (LDG.128 half-warp row locality preserved).
// Output: [C,G,K] features, [4,G,K] gpf, [G] mask (float 1/0).

#define ZDIM 40
#define YDIM 400
#define XDIM 400
#define KK 64
#define CC 64
#define TPB 256
#define NBLK 1184        // 148 SMs x 8 resident blocks
#define TS 65            // tile row stride (floats)

__global__ __launch_bounds__(TPB, 8) void grouper_kernel(
    const int* __restrict__ vox,     // [N,Z,Y,X]
    const int* __restrict__ gpos,    // [G,4]
    const float* __restrict__ feat,  // [M,C]
    const int* __restrict__ off,     // [K,4]
    float* __restrict__ out,
    int G)
{
    __shared__ int      s_idx[2][KK];
    __shared__ unsigned s_ball[2][2];
    __shared__ float    s_tile[KK * TS];

    const int t    = threadIdx.x;
    const int w    = t >> 5;
    const int lane = t & 31;
    const size_t GK = (size_t)G * KK;
    float* out_gpf  = out + (size_t)CC * GK;
    float* out_mask = out + (size_t)(CC + 4) * GK;
    const float4* feat4 = reinterpret_cast<const float4*>(feat);

    // loop-invariant per-thread constants
    const int gpf_ch = t >> 6;           // 0..3
    const int gpf_k  = t & 63;
    const float gpf_val = (float)off[gpf_k * 4 + gpf_ch];
    int4 of = make_int4(0, 0, 0, 0);
    if (t < KK) of = reinterpret_cast<const int4*>(off)[t];

    // drain mapping (conflict-free): lane -> (ql, dc)
    const int ql = lane & 7;             // k-quad low bits
    const int dc = lane >> 3;            // 0..3 c offset

    // ---- prologue: lookup for first g ----
    int g = blockIdx.x;
    if (t < KK) {
        const int4 gp = reinterpret_cast<const int4*>(gpos)[g];
        int z = min(max(gp.y + of.y, 0), ZDIM - 1);
        int y = min(max(gp.z + of.z, 0), YDIM - 1);
        int x = min(max(gp.w + of.w, 0), XDIM - 1);
        int idx = vox[((gp.x * ZDIM + z) * YDIM + y) * XDIM + x];
        s_idx[0][t] = idx;
        unsigned m = __ballot_sync(0xffffffffu, idx >= 0);
        if (lane == 0) s_ball[0][w] = m;
    }
    __syncthreads();

    int p = 0;
    for (; g < G; g += NBLK) {
        const int g_next = g + NBLK;
        const bool has_next = (g_next < G);

        // ---- prefetch next g's voxel lookups into registers ----
        int idxnext = -1;
        if (t < KK && has_next) {
            const int4 gp = reinterpret_cast<const int4*>(gpos)[g_next];
            int z = min(max(gp.y + of.y, 0), ZDIM - 1);
            int y = min(max(gp.z + of.z, 0), YDIM - 1);
            int x = min(max(gp.w + of.w, 0), XDIM - 1);
            idxnext = vox[((gp.x * ZDIM + z) * YDIM + y) * XDIM + x];
        }

        // ---- gather current g (round-6 mapping, unchanged) ----
#pragma unroll
        for (int j = 0; j < 4; j++) {
            const int job = t + TPB * j;     // 0..1023
            const int k   = job >> 4;        // 0..63
            const int cq  = job & 15;
            const int idx = s_idx[p][k];
            float4 v = make_float4(0.f, 0.f, 0.f, 0.f);
            if (idx >= 0) v = feat4[(size_t)idx * (CC / 4) + cq];
            float* dst = &s_tile[k * TS + cq * 4];
            dst[0] = v.x; dst[1] = v.y; dst[2] = v.z; dst[3] = v.w;
        }
        __syncthreads();

        // ---- drain: transposed float4 streaming stores, CF LDS ----
#pragma unroll
        for (int j = 0; j < 4; j++) {
            const int task = w * 4 + j;              // 0..31
            const int c0   = (task & 15) * 4;        // 0..60
            const int qh   = task >> 4;              // 0..1
            const int q    = qh * 8 + ql;            // 0..15
            const int c    = c0 + dc;
            float4 v;
            v.x = s_tile[(q * 4 + 0) * TS + c];
            v.y = s_tile[(q * 4 + 1) * TS + c];
            v.z = s_tile[(q * 4 + 2) * TS + c];
            v.w = s_tile[(q * 4 + 3) * TS + c];
            __stcs(reinterpret_cast<float4*>(
                       out + (size_t)c * GK + (size_t)g * KK + q * 4), v);
        }

        // ---- gpf + mask for current g ----
        __stcs(out_gpf + (size_t)gpf_ch * GK + (size_t)g * KK + gpf_k, gpf_val);
        if (t == 0)
            out_mask[g] = ((s_ball[p][0] | s_ball[p][1]) == 0u) ? 1.0f : 0.0f;

        // ---- publish prefetched lookups into the other buffer ----
        if (t < KK && has_next) {
            s_idx[1 - p][t] = idxnext;
            unsigned m = __ballot_sync(0xffffffffu, idxnext >= 0);
            if (lane == 0) s_ball[1 - p][w] = m;
        }
        __syncthreads();
        p ^= 1;
    }
}

extern "C" void kernel_launch(void* const* d_in, const int* in_sizes, int n_in,
                              void* d_out, int out_size) {
    const int*   vox  = (const int*)d_in[0];
    const int*   gpos = (const int*)d_in[1];
    const float* feat = (const float*)d_in[2];
    const int*   off  = (const int*)d_in[3];
    float* out = (float*)d_out;

    const int G = in_sizes[1] / 4;   // 30000
    grouper_kernel<<<NBLK, TPB>>>(vox, gpos, feat, off, out, G);
}